// round 1
// baseline (speedup 1.0000x reference)
#include <cuda_runtime.h>
#include <cuda_bf16.h>

// SparseDualFlow: reference runs a 100-iter Nesterov proximal loop per element.
// Closed-form analysis (see commit message / round notes):
//   next_acc  = 0.882*acc + 0.02*flow - 0.01*d
//   next_flow = relu(0.98*flow - 0.882*acc + 0.01*d)
// is linear; relu never clips for d>0 (min flow_t = 0.01*d at t=1) and flow==0
// forever for d<=0. Global convergence flag cannot fire before t~133 > 100.
// => flow_100 = K * max(d, 0), K from running the exact recurrence with d=1.

__global__ void sparse_dual_flow_kernel(const float4* __restrict__ in,
                                        float4* __restrict__ out,
                                        float K, int n4) {
    int i = blockIdx.x * blockDim.x + threadIdx.x;
    if (i < n4) {
        float4 d = in[i];
        float4 r;
        r.x = fmaxf(K * d.x, 0.0f);
        r.y = fmaxf(K * d.y, 0.0f);
        r.z = fmaxf(K * d.z, 0.0f);
        r.w = fmaxf(K * d.w, 0.0f);
        out[i] = r;
    }
}

__global__ void sparse_dual_flow_tail(const float* __restrict__ in,
                                      float* __restrict__ out,
                                      float K, int start, int n) {
    int i = start + blockIdx.x * blockDim.x + threadIdx.x;
    if (i < n) out[i] = fmaxf(K * in[i], 0.0f);
}

static float compute_K() {
    // Run the exact reference recurrence (reference op order) in double with d=1.
    const double STEP_SIZE = 0.01, MOMENTUM = 0.9;
    double flow = 0.0, acc = 0.0;
    for (int t = 0; t < 100; ++t) {
        double acc_m = MOMENTUM * acc;
        double gradient = 2.0 * (flow - acc_m) - 1.0;  // d = 1
        double next_acc = acc_m + STEP_SIZE * gradient;
        double next_flow = flow - next_acc;
        if (next_flow < 0.0) next_flow = 0.0;
        flow = next_flow;
        acc = next_acc;
    }
    return (float)flow;
}

extern "C" void kernel_launch(void* const* d_in, const int* in_sizes, int n_in,
                              void* d_out, int out_size) {
    const float* dual = (const float*)d_in[0];
    float* out = (float*)d_out;
    int n = in_sizes[0];

    float K = compute_K();  // host-side, baked as kernel arg at capture time

    int n4 = n / 4;
    if (n4 > 0) {
        int threads = 256;
        int blocks = (n4 + threads - 1) / threads;
        sparse_dual_flow_kernel<<<blocks, threads>>>(
            (const float4*)dual, (float4*)out, K, n4);
    }
    int rem = n - n4 * 4;
    if (rem > 0) {
        sparse_dual_flow_tail<<<1, 64>>>(dual, out, K, n4 * 4, n);
    }
}

// round 3
// speedup vs baseline: 1.0966x; 1.0966x over previous
#include <cuda_runtime.h>
#include <cuda_bf16.h>

// SparseDualFlow: reference = 100-iter Nesterov proximal loop per element.
// The recurrence is linear per element; relu never clips for d>0 and flow==0
// for d<=0; the global convergence flag can't fire before iter ~133 > 100.
// => flow_100 = K * max(d, 0). K computed host-side from the exact recurrence.
//
// R3 (= R2 resubmit; R2 died to infra, no metrics): baseline streaming kernel
// was DRAM=59% with MLP_p1=1. Batch 4x float4 loads per thread (MLP=4) +
// streaming cache hints (__ldcs/__stcs) to approach the LTS cap (~6300 B/cyc).

#define BATCH 4

__global__ void sparse_dual_flow_kernel(const float4* __restrict__ in,
                                        float4* __restrict__ out,
                                        float K, int n4) {
    int base = blockIdx.x * (blockDim.x * BATCH) + threadIdx.x;
    float4 v[BATCH];

    // Fast path: whole tile in range (always true for n = 2^24)
    if (base + (BATCH - 1) * blockDim.x < n4) {
        #pragma unroll
        for (int k = 0; k < BATCH; ++k)
            v[k] = __ldcs(&in[base + k * blockDim.x]);   // front-batched: MLP=4
        #pragma unroll
        for (int k = 0; k < BATCH; ++k) {
            float4 r;
            r.x = fmaxf(K * v[k].x, 0.0f);
            r.y = fmaxf(K * v[k].y, 0.0f);
            r.z = fmaxf(K * v[k].z, 0.0f);
            r.w = fmaxf(K * v[k].w, 0.0f);
            __stcs(&out[base + k * blockDim.x], r);
        }
    } else {
        #pragma unroll
        for (int k = 0; k < BATCH; ++k) {
            int i = base + k * blockDim.x;
            if (i < n4) {
                float4 d = __ldcs(&in[i]);
                float4 r;
                r.x = fmaxf(K * d.x, 0.0f);
                r.y = fmaxf(K * d.y, 0.0f);
                r.z = fmaxf(K * d.z, 0.0f);
                r.w = fmaxf(K * d.w, 0.0f);
                __stcs(&out[i], r);
            }
        }
    }
}

__global__ void sparse_dual_flow_tail(const float* __restrict__ in,
                                      float* __restrict__ out,
                                      float K, int start, int n) {
    int i = start + blockIdx.x * blockDim.x + threadIdx.x;
    if (i < n) out[i] = fmaxf(K * in[i], 0.0f);
}

static float compute_K() {
    // Exact reference recurrence (reference op order) in double with d = 1.
    const double STEP_SIZE = 0.01, MOMENTUM = 0.9;
    double flow = 0.0, acc = 0.0;
    for (int t = 0; t < 100; ++t) {
        double acc_m = MOMENTUM * acc;
        double gradient = 2.0 * (flow - acc_m) - 1.0;  // d = 1
        double next_acc = acc_m + STEP_SIZE * gradient;
        double next_flow = flow - next_acc;
        if (next_flow < 0.0) next_flow = 0.0;
        flow = next_flow;
        acc = next_acc;
    }
    return (float)flow;
}

extern "C" void kernel_launch(void* const* d_in, const int* in_sizes, int n_in,
                              void* d_out, int out_size) {
    const float* dual = (const float*)d_in[0];
    float* out = (float*)d_out;
    int n = in_sizes[0];

    float K = compute_K();  // host-side, baked as kernel arg at capture time

    int n4 = n / 4;
    if (n4 > 0) {
        const int threads = 256;
        int tile = threads * BATCH;
        int blocks = (n4 + tile - 1) / tile;
        sparse_dual_flow_kernel<<<blocks, threads>>>(
            (const float4*)dual, (float4*)out, K, n4);
    }
    int rem = n - n4 * 4;
    if (rem > 0) {
        sparse_dual_flow_tail<<<1, 64>>>(dual, out, K, n4 * 4, n);
    }
}

// round 6
// speedup vs baseline: 1.1810x; 1.0769x over previous
#include <cuda_runtime.h>
#include <cuda_bf16.h>

// SparseDualFlow: reference = 100-iter Nesterov proximal loop per element.
// Linear recurrence per element; relu never clips for d>0, flow==0 for d<=0,
// global convergence flag can't fire before iter ~133 > 100.
// => flow_100 = K * max(d, 0). K computed host-side (exact recurrence, d=1).
//
// R6 (= R4/R5 resubmit; both died to infra, no metrics; failure mode shown
// uncorrelated with kernel content -- same source failed R2 and passed R3):
// R3 showed apparent throughput 7.19 TB/s (134.2MB/18.66us), ~90% of HBM
// spec; ncu DRAM=56% is writeback-skewed (L2 absorbs the write stream).
// Near the streaming floor. Last small lever: BATCH=8 to shrink the wave
// tail, 8 loads in flight per thread.

#define BATCH 8

__global__ void sparse_dual_flow_kernel(const float4* __restrict__ in,
                                        float4* __restrict__ out,
                                        float K, int n4) {
    int base = blockIdx.x * (blockDim.x * BATCH) + threadIdx.x;

    if (base + (BATCH - 1) * blockDim.x < n4) {   // fast path (always, n = 2^24)
        float4 v[BATCH];
        #pragma unroll
        for (int k = 0; k < BATCH; ++k)
            v[k] = __ldcs(&in[base + k * blockDim.x]);   // front-batched loads
        #pragma unroll
        for (int k = 0; k < BATCH; ++k) {
            float4 r;
            r.x = fmaxf(K * v[k].x, 0.0f);
            r.y = fmaxf(K * v[k].y, 0.0f);
            r.z = fmaxf(K * v[k].z, 0.0f);
            r.w = fmaxf(K * v[k].w, 0.0f);
            __stcs(&out[base + k * blockDim.x], r);
        }
    } else {
        #pragma unroll
        for (int k = 0; k < BATCH; ++k) {
            int i = base + k * blockDim.x;
            if (i < n4) {
                float4 d = __ldcs(&in[i]);
                float4 r;
                r.x = fmaxf(K * d.x, 0.0f);
                r.y = fmaxf(K * d.y, 0.0f);
                r.z = fmaxf(K * d.z, 0.0f);
                r.w = fmaxf(K * d.w, 0.0f);
                __stcs(&out[i], r);
            }
        }
    }
}

__global__ void sparse_dual_flow_tail(const float* __restrict__ in,
                                      float* __restrict__ out,
                                      float K, int start, int n) {
    int i = start + blockIdx.x * blockDim.x + threadIdx.x;
    if (i < n) out[i] = fmaxf(K * in[i], 0.0f);
}

static float compute_K() {
    // Exact reference recurrence (reference op order) in double with d = 1.
    const double STEP_SIZE = 0.01, MOMENTUM = 0.9;
    double flow = 0.0, acc = 0.0;
    for (int t = 0; t < 100; ++t) {
        double acc_m = MOMENTUM * acc;
        double gradient = 2.0 * (flow - acc_m) - 1.0;  // d = 1
        double next_acc = acc_m + STEP_SIZE * gradient;
        double next_flow = flow - next_acc;
        if (next_flow < 0.0) next_flow = 0.0;
        flow = next_flow;
        acc = next_acc;
    }
    return (float)flow;
}

extern "C" void kernel_launch(void* const* d_in, const int* in_sizes, int n_in,
                              void* d_out, int out_size) {
    const float* dual = (const float*)d_in[0];
    float* out = (float*)d_out;
    int n = in_sizes[0];

    float K = compute_K();  // host-side, baked as kernel arg at capture time

    int n4 = n / 4;
    if (n4 > 0) {
        const int threads = 256;
        int tile = threads * BATCH;
        int blocks = (n4 + tile - 1) / tile;
        sparse_dual_flow_kernel<<<blocks, threads>>>(
            (const float4*)dual, (float4*)out, K, n4);
    }
    int rem = n - n4 * 4;
    if (rem > 0) {
        sparse_dual_flow_tail<<<1, 64>>>(dual, out, K, n4 * 4, n);
    }
}